// round 5
// baseline (speedup 1.0000x reference)
#include <cuda_runtime.h>

// prediction: [32,4,512,512] f32 ; intervals: [32,4,64,2,2] i32 (x2 tensors)
// loss = 14.0 + sum w(comp,c,n)*(birth-death)^2
//   g = GOOD_comp[c]; w = -0.0625/g if n<g else +0.0625/(64-g)
// GOOD_0={1,2,1,3} -> nibbles 0x3121 ; GOOD_1={1,0,2,1} -> 0x1201

#define NBC 128

__device__ float    g_partials[NBC];
__device__ unsigned g_count = 0;   // wraps to 0 every 128 arrivals -> replay-safe

__global__ void __launch_bounds__(128, 1)
bd_fused_kernel(const float* __restrict__ pred,
                const int*   __restrict__ iv0,
                const int*   __restrict__ iv1,
                float*       __restrict__ out)
{
    const int bc   = blockIdx.x;      // b*4 + c
    const int c    = bc & 3;
    const int tid  = threadIdx.x;     // 0..127
    const int comp = tid >> 6;
    const int n    = tid & 63;

    const int* iv = comp ? iv1 : iv0;
    const int4 co = reinterpret_cast<const int4*>(iv)[bc * 64 + n];

    const float* p = pred + (size_t)bc * (512 * 512);
    const float birth = __ldg(p + ((co.x << 9) | co.y));
    const float death = __ldg(p + ((co.z << 9) | co.w));
    const float d = birth - death;

    const unsigned packed = comp ? 0x1201u : 0x3121u;
    const int g = (packed >> (c * 4)) & 0xF;
    const float w = (n < g) ? (-0.0625f / (float)g)
                            : ( 0.0625f / (float)(64 - g));
    float v = w * d * d;

    #pragma unroll
    for (int off = 16; off > 0; off >>= 1)
        v += __shfl_down_sync(0xFFFFFFFFu, v, off);

    __shared__ float s[4];
    __shared__ int   s_last;
    if ((tid & 31) == 0) s[tid >> 5] = v;
    __syncthreads();

    if (tid == 0) {
        g_partials[bc] = s[0] + s[1] + s[2] + s[3];
        __threadfence();                             // publish partial
        unsigned old = atomicInc(&g_count, NBC - 1); // wraps -> self-reset
        s_last = (old == NBC - 1);
    }
    __syncthreads();

    if (s_last) {
        // This block saw all 127 others arrive; their partials are visible.
        float pv = __ldcg(&g_partials[tid]);         // L2 read, skip L1
        #pragma unroll
        for (int off = 16; off > 0; off >>= 1)
            pv += __shfl_down_sync(0xFFFFFFFFu, pv, off);
        if ((tid & 31) == 0) s[tid >> 5] = pv;
        __syncthreads();
        if (tid == 0)
            out[0] = s[0] + s[1] + s[2] + s[3] + 14.0f;
    }
}

extern "C" void kernel_launch(void* const* d_in, const int* in_sizes, int n_in,
                              void* d_out, int out_size)
{
    const float* pred = (const float*)d_in[0];
    const int*   iv0  = (const int*)d_in[1];
    const int*   iv1  = (const int*)d_in[2];
    bd_fused_kernel<<<NBC, 128>>>(pred, iv0, iv1, (float*)d_out);
}

// round 6
// speedup vs baseline: 1.5459x; 1.5459x over previous
#include <cuda_runtime.h>

// prediction: [32,4,512,512] f32 ; intervals: [32,4,64,2,2] i32 (x2 tensors)
// loss = 14.0 + sum w(comp,c,n)*(birth-death)^2
//   g = GOOD_comp[c]; w = -0.0625/g if n<g else +0.0625/(64-g)
// GOOD_0={1,2,1,3} -> nibbles 0x3121 ; GOOD_1={1,0,2,1} -> 0x1201

#define NBC 128

__device__ float    g_accum = 0.0f;  // reset by last block each run
__device__ unsigned g_count = 0;     // atom.inc wraps at 128 arrivals -> replay-safe

__global__ void __launch_bounds__(128, 1)
bd_fused2_kernel(const float* __restrict__ pred,
                 const int*   __restrict__ iv0,
                 const int*   __restrict__ iv1,
                 float*       __restrict__ out)
{
    const int bc   = blockIdx.x;      // b*4 + c
    const int c    = bc & 3;
    const int tid  = threadIdx.x;     // 0..127
    const int comp = tid >> 6;
    const int n    = tid & 63;

    const int* iv = comp ? iv1 : iv0;
    const int4 co = reinterpret_cast<const int4*>(iv)[bc * 64 + n];

    const float* p = pred + (size_t)bc * (512 * 512);
    const float birth = __ldg(p + ((co.x << 9) | co.y));
    const float death = __ldg(p + ((co.z << 9) | co.w));
    const float d = birth - death;

    const unsigned packed = comp ? 0x1201u : 0x3121u;
    const int g = (packed >> (c * 4)) & 0xF;
    const float w = (n < g) ? (-0.0625f / (float)g)
                            : ( 0.0625f / (float)(64 - g));
    float v = w * d * d;

    // Warp reduce, then 4 warp partials through smem.
    #pragma unroll
    for (int off = 16; off > 0; off >>= 1)
        v += __shfl_down_sync(0xFFFFFFFFu, v, off);

    __shared__ float s[4];
    if ((tid & 31) == 0) s[tid >> 5] = v;
    __syncthreads();

    if (tid == 0) {
        const float partial = s[0] + s[1] + s[2] + s[3];
        // Release-reduction: publishes partial without a MEMBAR.
        asm volatile("red.release.gpu.global.add.f32 [%0], %1;"
                     :: "l"(&g_accum), "f"(partial) : "memory");
        // Acq-rel arrival counter; RMW chain makes all release-adds visible
        // to the last arriver. Wraps to 0 after 128 arrivals (replay-safe).
        unsigned old;
        asm volatile("atom.acq_rel.gpu.global.inc.u32 %0, [%1], %2;"
                     : "=r"(old) : "l"(&g_count), "r"(NBC - 1u) : "memory");
        if (old == NBC - 1u) {
            float acc;
            asm volatile("ld.acquire.gpu.global.f32 %0, [%1];"
                         : "=f"(acc) : "l"(&g_accum) : "memory");
            out[0] = acc + 14.0f;
            // Reset for next replay; visible at next launch boundary.
            asm volatile("st.global.f32 [%0], 0f00000000;"
                         :: "l"(&g_accum) : "memory");
        }
    }
}

extern "C" void kernel_launch(void* const* d_in, const int* in_sizes, int n_in,
                              void* d_out, int out_size)
{
    const float* pred = (const float*)d_in[0];
    const int*   iv0  = (const int*)d_in[1];
    const int*   iv1  = (const int*)d_in[2];
    bd_fused2_kernel<<<NBC, 128>>>(pred, iv0, iv1, (float*)d_out);
}